// round 14
// baseline (speedup 1.0000x reference)
#include <cuda_runtime.h>
#include <cuda_bf16.h>
#include <mma.h>
#include <math.h>
#include <stdint.h>

using namespace nvcuda;

// Problem constants (B=2, S=1024, D=1024, V=32000, K=16)
#define N_ROWS 2048
#define DIM    1024
#define VOCAB  32000
#define TOPK   16
#define KTOT   2048   // 2*DIM
#define DTILES 8      // DIM/128
#define HALF_ROWS (N_ROWS / 2)

// Scratch (device globals; no allocation allowed)
__device__ __align__(128) __nv_bfloat16 g_merged_h[N_ROWS * DIM];
__device__ __align__(128) __nv_bfloat16 g_hidden_h[N_ROWS * DIM];
__device__ __align__(128) __nv_bfloat16 g_mW1_h[DIM * KTOT];
__device__ __align__(128) float g_ch[N_ROWS * DIM];      // hidden-half preacts
__device__ __align__(128) float g_probs[N_ROWS * TOPK];
__device__ __align__(128) float g_zpart[N_ROWS * DTILES];

// ---------------------------------------------------------------------------
// f32 -> bf16 bulk convert (8 elems per iter)
// ---------------------------------------------------------------------------
__global__ __launch_bounds__(256) void conv_kernel(
    const float* __restrict__ src, __nv_bfloat16* __restrict__ dst, int n8)
{
    for (int i = blockIdx.x * 256 + threadIdx.x; i < n8; i += gridDim.x * 256) {
        float4 a = ((const float4*)src)[2 * i];
        float4 b = ((const float4*)src)[2 * i + 1];
        __nv_bfloat162 t0 = __floats2bfloat162_rn(a.x, a.y);
        __nv_bfloat162 t1 = __floats2bfloat162_rn(a.z, a.w);
        __nv_bfloat162 t2 = __floats2bfloat162_rn(b.x, b.y);
        __nv_bfloat162 t3 = __floats2bfloat162_rn(b.z, b.w);
        uint4 u;
        u.x = *(unsigned*)&t0; u.y = *(unsigned*)&t1;
        u.z = *(unsigned*)&t2; u.w = *(unsigned*)&t3;
        ((uint4*)dst)[i] = u;
    }
}

// ---------------------------------------------------------------------------
// Kernel A: per-row prep (unchanged).
// ---------------------------------------------------------------------------
__global__ __launch_bounds__(256) void prep_kernel(
    const float* __restrict__ hidden,
    const float* __restrict__ dist,
    const float* __restrict__ sh,
    const float* __restrict__ bW,
    const float* __restrict__ bb)
{
    const int n = blockIdx.x;
    __shared__ __nv_bfloat16 s_sh[TOPK * DIM];   // 32 KB
    __shared__ float s_probs[TOPK];
    __shared__ float sred[8];

    const int tid = threadIdx.x, lane = tid & 31;
    const float4* sh4 = (const float4*)(sh + (size_t)n * (TOPK * DIM));
    const float4* bW4 = (const float4*)bW;

    float acc = 0.f;
    #pragma unroll 4
    for (int i = tid; i < TOPK * DIM / 4; i += 256) {
        float4 v = sh4[i];
        float4 w = __ldg(&bW4[DIM / 4 + (i & (DIM / 4 - 1))]);
        acc += v.x * w.x + v.y * w.y + v.z * w.z + v.w * w.w;
        __nv_bfloat162 p0 = __floats2bfloat162_rn(v.x, v.y);
        __nv_bfloat162 p1 = __floats2bfloat162_rn(v.z, v.w);
        uint2 u; u.x = *(unsigned*)&p0; u.y = *(unsigned*)&p1;
        *(uint2*)(s_sh + 4 * i) = u;
    }
    acc *= (1.f / (float)TOPK);

    {
        float4 v = ((const float4*)(hidden + (size_t)n * DIM))[tid];
        float4 w = __ldg(&bW4[tid]);
        acc += v.x * w.x + v.y * w.y + v.z * w.z + v.w * w.w;
    }

    #pragma unroll
    for (int o = 16; o > 0; o >>= 1)
        acc += __shfl_xor_sync(0xffffffffu, acc, o);
    if (lane == 0) sred[tid >> 5] = acc;
    __syncthreads();

    if (tid < 32) {
        float tot = sred[0] + sred[1] + sred[2] + sred[3]
                  + sred[4] + sred[5] + sred[6] + sred[7];
        float bwv = expf(tot + __ldg(&bb[0]));

        int k = lane & 15;
        float x = -__ldg(&dist[(size_t)n * TOPK + k]) / bwv;
        float mx = x, sm;
        #pragma unroll
        for (int o = 8; o > 0; o >>= 1)
            mx = fmaxf(mx, __shfl_xor_sync(0xffffffffu, mx, o, 16));
        float e = expf(x - mx);
        sm = e;
        #pragma unroll
        for (int o = 8; o > 0; o >>= 1)
            sm += __shfl_xor_sync(0xffffffffu, sm, o, 16);
        float p = e / sm;
        if (lane < 16) {
            s_probs[k] = p;
            g_probs[(size_t)n * TOPK + k] = p;
        }
    }
    __syncthreads();

    {
        const int i = tid;
        float mx_ = 0.f, my_ = 0.f, mz_ = 0.f, mw_ = 0.f;
        #pragma unroll
        for (int k = 0; k < TOPK; k++) {
            float p = s_probs[k];
            uint2 u = *(const uint2*)(s_sh + k * DIM + 4 * i);
            __nv_bfloat162 b0 = *(__nv_bfloat162*)&u.x;
            __nv_bfloat162 b1 = *(__nv_bfloat162*)&u.y;
            float2 f0 = __bfloat1622float2(b0);
            float2 f1 = __bfloat1622float2(b1);
            mx_ = fmaf(p, f0.x, mx_); my_ = fmaf(p, f0.y, my_);
            mz_ = fmaf(p, f1.x, mz_); mw_ = fmaf(p, f1.y, mw_);
        }
        __nv_bfloat162 p0 = __floats2bfloat162_rn(mx_, my_);
        __nv_bfloat162 p1 = __floats2bfloat162_rn(mz_, mw_);
        uint2 u; u.x = *(unsigned*)&p0; u.y = *(unsigned*)&p1;
        *(uint2*)(g_merged_h + (size_t)n * DIM + 4 * i) = u;
    }
}

// ---------------------------------------------------------------------------
// Kernel B: half-GEMM, bf16 HMMA, 3-stage cp.async pipeline. rowbase param
// allows row-half splits of phase 1.
// ---------------------------------------------------------------------------
#define GP 72
#define GSTAGE (128 * GP)
#define GEMM_SMEM (3 * 2 * GSTAGE * 2)    // 110592 B
#define NCH 16

__device__ __forceinline__ void cp16(uint32_t saddr, const void* g) {
    asm volatile("cp.async.cg.shared.global [%0], [%1], 16;"
                 :: "r"(saddr), "l"(__cvta_generic_to_global(g)));
}

__global__ __launch_bounds__(256, 1) void gemm_kernel(
    const __nv_bfloat16* __restrict__ Ah,
    const float* __restrict__ mb1,
    const float* __restrict__ mW2,
    int kbase, int phase, int rowbase)
{
    extern __shared__ __align__(16) char smem_raw[];
    __nv_bfloat16* smem_h = (__nv_bfloat16*)smem_raw;
    uint32_t sbase;
    asm("{ .reg .u64 t; cvta.to.shared.u64 t, %1; cvt.u32.u64 %0, t; }"
        : "=r"(sbase) : "l"(smem_raw));

    const int tid  = threadIdx.x;
    const int wid  = tid >> 5, lane = tid & 31;
    const int rowTile = rowbase + blockIdx.x;
    const int dTile   = blockIdx.y;
    const int warpM = wid >> 2;
    const int warpN = wid & 3;

    wmma::fragment<wmma::accumulator, 16, 16, 16, float> c[4][2];
    #pragma unroll
    for (int mi = 0; mi < 4; mi++)
        #pragma unroll
        for (int ni = 0; ni < 2; ni++)
            wmma::fill_fragment(c[mi][ni], 0.f);

    const __nv_bfloat16* Bh = g_mW1_h;

    auto issue = [&](int it) {
        const int buf = it % 3;
        const uint32_t sA = sbase + buf * 2 * GSTAGE * 2;
        const uint32_t sB = sA + GSTAGE * 2;
        #pragma unroll
        for (int j = 0; j < 4; j++) {
            int idx = tid + 256 * j;
            int row = idx >> 3, qc = idx & 7;
            cp16(sA + (row * GP + qc * 8) * 2,
                 Ah + (size_t)(rowTile * 128 + row) * DIM + it * 64 + qc * 8);
            cp16(sB + (row * GP + qc * 8) * 2,
                 Bh + (size_t)(dTile * 128 + row) * KTOT + kbase + it * 64 + qc * 8);
        }
        asm volatile("cp.async.commit_group;" ::: "memory");
    };

    issue(0);
    issue(1);
    for (int it = 0; it < NCH; ++it) {
        if (it + 1 < NCH)
            asm volatile("cp.async.wait_group 1;" ::: "memory");
        else
            asm volatile("cp.async.wait_group 0;" ::: "memory");
        __syncthreads();

        const __nv_bfloat16* As = smem_h + (it % 3) * 2 * GSTAGE;
        const __nv_bfloat16* Bs = As + GSTAGE;
        #pragma unroll
        for (int kk = 0; kk < 4; kk++) {
            wmma::fragment<wmma::matrix_a, 16, 16, 16, __nv_bfloat16, wmma::row_major> a[4];
            wmma::fragment<wmma::matrix_b, 16, 16, 16, __nv_bfloat16, wmma::col_major> b[2];
            #pragma unroll
            for (int mi = 0; mi < 4; mi++)
                wmma::load_matrix_sync(a[mi], As + (warpM * 64 + mi * 16) * GP + kk * 16, GP);
            #pragma unroll
            for (int ni = 0; ni < 2; ni++)
                wmma::load_matrix_sync(b[ni], Bs + (warpN * 32 + ni * 16) * GP + kk * 16, GP);
            #pragma unroll
            for (int mi = 0; mi < 4; mi++)
                #pragma unroll
                for (int ni = 0; ni < 2; ni++)
                    wmma::mma_sync(c[mi][ni], a[mi], b[ni], c[mi][ni]);
        }
        if (it + 2 < NCH) issue(it + 2);
    }
    __syncthreads();

    float* fbuf  = (float*)smem_raw;
    float* scr   = fbuf + wid * 320;
    float* zrows = fbuf + 8 * 320;
    const int r16 = lane & 15, half = lane >> 4;

    if (phase == 0) {
        #pragma unroll
        for (int mi = 0; mi < 4; mi++) {
            #pragma unroll
            for (int ni = 0; ni < 2; ni++) {
                wmma::store_matrix_sync(scr, c[mi][ni], 20, wmma::mem_row_major);
                __syncwarp();
                int grow = rowTile * 128 + warpM * 64 + mi * 16 + r16;
                int gcol = dTile * 128 + warpN * 32 + ni * 16 + half * 8;
                *(float4*)(g_ch + (size_t)grow * DIM + gcol) =
                    *(float4*)(scr + r16 * 20 + half * 8);
                *(float4*)(g_ch + (size_t)grow * DIM + gcol + 4) =
                    *(float4*)(scr + r16 * 20 + half * 8 + 4);
                __syncwarp();
            }
        }
    } else {
        float zacc[4] = {0.f, 0.f, 0.f, 0.f};
        #pragma unroll
        for (int mi = 0; mi < 4; mi++) {
            #pragma unroll
            for (int ni = 0; ni < 2; ni++) {
                wmma::store_matrix_sync(scr, c[mi][ni], 20, wmma::mem_row_major);
                __syncwarp();
                int grow = rowTile * 128 + warpM * 64 + mi * 16 + r16;
                int gc0  = dTile * 128 + warpN * 32 + ni * 16 + half * 8;
                const float* chs = g_ch + (size_t)grow * DIM + gc0;
                float z = 0.f;
                #pragma unroll
                for (int cc = 0; cc < 8; cc++) {
                    float v = scr[r16 * 20 + half * 8 + cc] + chs[cc] + __ldg(&mb1[gc0 + cc]);
                    z = fmaf(fmaxf(v, 0.f), __ldg(&mW2[gc0 + cc]), z);
                }
                z += __shfl_xor_sync(0xffffffffu, z, 16);
                zacc[mi] += z;
                __syncwarp();
            }
        }
        if (lane < 16) {
            #pragma unroll
            for (int mi = 0; mi < 4; mi++)
                zrows[(warpM * 64 + mi * 16 + lane) * 4 + warpN] = zacc[mi];
        }
        __syncthreads();
        if (tid < 128) {
            float zz = zrows[tid * 4 + 0] + zrows[tid * 4 + 1]
                     + zrows[tid * 4 + 2] + zrows[tid * 4 + 3];
            g_zpart[(size_t)(rowTile * 128 + tid) * DTILES + dTile] = zz;
        }
    }
}

// ---------------------------------------------------------------------------
// Kernel C (fused): per-row two-pass output. Pass 1 reads the 128KB row
// (stays L2-resident: <=4 blocks/SM x 148 x 128KB ~= 75MB < 126MB L2) and
// computes sumexp + m + C. Pass 2 re-reads from L2, writes out evict-first.
// Warp 0 then applies the <=16 scattered top-k fixups.
// ---------------------------------------------------------------------------
__device__ __forceinline__ void stcs4(float4* p, float4 v) {
    asm volatile("st.global.cs.v4.f32 [%0], {%1,%2,%3,%4};"
                 :: "l"(__cvta_generic_to_global(p)),
                    "f"(v.x), "f"(v.y), "f"(v.z), "f"(v.w));
}

__global__ __launch_bounds__(512) void out_kernel(
    const float* __restrict__ logits,
    const void* __restrict__ tok,
    const float* __restrict__ mb2,
    float* __restrict__ out, int nbase)
{
    const int n = nbase + blockIdx.x;
    const int tid = threadIdx.x, lane = tid & 31, wid = tid >> 5;
    __shared__ float ss_[16];
    __shared__ float s_C, s_m, s_sum;

    const float4* l4 = (const float4*)(logits + (size_t)n * VOCAB);

    // Pass 1: sum of exp (no max pass; logits O(+-10), overflow-safe).
    float ax = 0.f, ay = 0.f, az = 0.f, aw = 0.f;
    #pragma unroll 4
    for (int i = tid; i < VOCAB / 4; i += 512) {
        float4 v = l4[i];
        ax += expf(v.x); ay += expf(v.y);
        az += expf(v.z); aw += expf(v.w);
    }
    float s = (ax + ay) + (az + aw);
    #pragma unroll
    for (int o = 16; o > 0; o >>= 1)
        s += __shfl_xor_sync(0xffffffffu, s, o);
    if (lane == 0) ss_[wid] = s;
    __syncthreads();

    if (tid < 32) {
        float v = (lane < 16) ? ss_[lane] : 0.f;
        #pragma unroll
        for (int o = 8; o > 0; o >>= 1)
            v += __shfl_xor_sync(0xffffffffu, v, o, 16);
        // zpart reduce in lanes 0..7
        float zp = (lane < 8) ? g_zpart[(size_t)n * DTILES + lane] : 0.f;
        #pragma unroll
        for (int o = 4; o > 0; o >>= 1)
            zp += __shfl_xor_sync(0xffffffffu, zp, o, 8);
        if (lane == 0) {
            float z = zp + __ldg(&mb2[0]);
            float m = 1.f / (1.f + expf(-z));
            s_m = m;
            s_sum = v;
            s_C = logf(v) - logf(1.f - m);   // out = lg - C
        }
    }
    __syncthreads();

    // Pass 2: re-read (L2 hit) and stream out.
    const float C = s_C;
    float4* o4 = (float4*)(out + (size_t)n * VOCAB);
    #pragma unroll 4
    for (int i = tid; i < VOCAB / 4; i += 512) {
        float4 v = l4[i];
        v.x -= C; v.y -= C; v.z -= C; v.w -= C;
        stcs4(o4 + i, v);
    }
    __syncthreads();   // order pass-2 stores before fixup overwrites

    // Fixup: warp 0, lane-parallel dedup via shfl.
    if (tid < 32) {
        const int* t32 = (const int*)tok;
        int is64 = 1;
        #pragma unroll
        for (int k = 0; k < TOPK; k++)
            if (t32[2 * k + 1] != 0) is64 = 0;

        const int k = lane & 15;
        int idx;
        if (is64) idx = (int)((const long long*)tok)[(size_t)n * TOPK + k];
        else      idx = t32[(size_t)n * TOPK + k];
        idx = min(max(idx, 0), VOCAB - 1);

        float m = s_m;
        float val = m * __ldg(&g_probs[(size_t)n * TOPK + k]);

        if (lane < 16) {
            bool first = true;
            float tot = 0.f;
            #pragma unroll
            for (int j = 0; j < 16; j++) {
                int   ij = __shfl_sync(0x0000ffffu, idx, j, 16);
                float vj = __shfl_sync(0x0000ffffu, val, j, 16);
                if (ij == idx) {
                    if (j < k) first = false;
                    tot += vj;
                }
            }
            if (first) {
                float lg = __ldg(&logits[(size_t)n * VOCAB + idx]);
                float p = expf(lg) / s_sum;
                out[(size_t)n * VOCAB + idx] = logf((1.f - m) * p + tot);
            }
        }
    }
}

// ---------------------------------------------------------------------------
// Host: fork-join; gemm1 split by row halves so the fused output tail for the
// low half starts while the high-half GEMM is still on the tensor pipe.
// 2 streams, 4 events (R13-proven budget).
// ---------------------------------------------------------------------------
extern "C" void kernel_launch(void* const* d_in, const int* in_sizes, int n_in,
                              void* d_out, int out_size)
{
    int i_logits = -1, i_sh = -1, i_bW = -1;
    int p2m[2] = {-1, -1};  int n2m = 0;
    int p32k[2] = {-1, -1}; int n32k = 0;
    int p1k[2] = {-1, -1};  int n1k = 0;
    int p1[2] = {-1, -1};   int n1 = 0;

    for (int i = 0; i < n_in; i++) {
        switch (in_sizes[i]) {
            case 65536000: i_logits = i; break;
            case 33554432: i_sh = i; break;
            case 2048:     i_bW = i; break;
            case 2097152:  if (n2m < 2) p2m[n2m++] = i; break;
            case 32768:    if (n32k < 2) p32k[n32k++] = i; break;
            case 1024:     if (n1k < 2) p1k[n1k++] = i; break;
            case 1:        if (n1 < 2) p1[n1++] = i; break;
            default: break;
        }
    }
    const bool alpha = (i_bW >= 0 && i_logits >= 0 && i_bW < i_logits);
    const int i_hidden = p2m[0],  i_mW1 = p2m[1];
    const int i_dist   = p32k[0], i_tok = p32k[1];
    const int i_bb     = p1[0],   i_mb2 = p1[1];
    const int i_mb1    = alpha ? p1k[1] : p1k[0];
    const int i_mW2    = alpha ? p1k[0] : p1k[1];

    const float* hidden = (const float*)d_in[i_hidden];
    const float* logits = (const float*)d_in[i_logits];
    const float* dist   = (const float*)d_in[i_dist];
    const float* sh     = (const float*)d_in[i_sh];
    const void*  tok    = d_in[i_tok];
    const float* bW     = (const float*)d_in[i_bW];
    const float* bb     = (const float*)d_in[i_bb];
    const float* mW1    = (const float*)d_in[i_mW1];
    const float* mb1    = (const float*)d_in[i_mb1];
    const float* mW2    = (const float*)d_in[i_mW2];
    const float* mb2    = (const float*)d_in[i_mb2];
    float*       out    = (float*)d_out;

    __nv_bfloat16 *hidden_h = nullptr, *mW1_h = nullptr, *merged_h = nullptr;
    cudaGetSymbolAddress((void**)&hidden_h, g_hidden_h);
    cudaGetSymbolAddress((void**)&mW1_h,   g_mW1_h);
    cudaGetSymbolAddress((void**)&merged_h, g_merged_h);

    cudaFuncSetAttribute(gemm_kernel, cudaFuncAttributeMaxDynamicSharedMemorySize, GEMM_SMEM);

    cudaStream_t s2;
    cudaStreamCreateWithFlags(&s2, cudaStreamNonBlocking);
    cudaEvent_t e0, e1, e2a, e2b;
    cudaEventCreateWithFlags(&e0,  cudaEventDisableTiming);
    cudaEventCreateWithFlags(&e1,  cudaEventDisableTiming);
    cudaEventCreateWithFlags(&e2a, cudaEventDisableTiming);
    cudaEventCreateWithFlags(&e2b, cudaEventDisableTiming);

    cudaEventRecord(e0, 0);
    cudaStreamWaitEvent(s2, e0, 0);

    // S2: converts -> full hidden-half GEMM (no prep dependency).
    conv_kernel<<<512, 256, 0, s2>>>(hidden, hidden_h, N_ROWS * DIM / 8);
    conv_kernel<<<512, 256, 0, s2>>>(mW1, mW1_h, DIM * KTOT / 8);
    gemm_kernel<<<dim3(16, 8), 256, GEMM_SMEM, s2>>>(hidden_h, mb1, mW2, 0, 0, 0);

    // Origin: prep (-> merged_h, probs).
    prep_kernel<<<N_ROWS, 256>>>(hidden, dist, sh, bW, bb);
    cudaEventRecord(e1, 0);

    // S2: merged-half GEMM split by row halves.
    cudaStreamWaitEvent(s2, e1, 0);
    gemm_kernel<<<dim3(8, 8), 256, GEMM_SMEM, s2>>>(merged_h, mb1, mW2, DIM, 1, 0);
    cudaEventRecord(e2a, s2);
    gemm_kernel<<<dim3(8, 8), 256, GEMM_SMEM, s2>>>(merged_h, mb1, mW2, DIM, 1, 8);
    cudaEventRecord(e2b, s2);

    // Origin: fused output tail per row half (all s2 work upstream of e2b).
    cudaStreamWaitEvent(0, e2a, 0);
    out_kernel<<<HALF_ROWS, 512>>>(logits, tok, mb2, out, 0);
    cudaStreamWaitEvent(0, e2b, 0);
    out_kernel<<<HALF_ROWS, 512>>>(logits, tok, mb2, out, HALF_ROWS);
}

// round 16
// speedup vs baseline: 1.0941x; 1.0941x over previous
#include <cuda_runtime.h>
#include <cuda_bf16.h>
#include <mma.h>
#include <math.h>
#include <stdint.h>

using namespace nvcuda;

// Problem constants (B=2, S=1024, D=1024, V=32000, K=16)
#define N_ROWS 2048
#define DIM    1024
#define VOCAB  32000
#define TOPK   16
#define KTOT   2048   // 2*DIM
#define DTILES 8      // DIM/128
#define HALF_ROWS (N_ROWS / 2)

// Scratch (device globals; no allocation allowed)
__device__ __align__(128) __nv_bfloat16 g_merged_h[N_ROWS * DIM];
__device__ __align__(128) __nv_bfloat16 g_hidden_h[N_ROWS * DIM];
__device__ __align__(128) __nv_bfloat16 g_mW1_h[DIM * KTOT];
__device__ __align__(128) float g_ch[N_ROWS * DIM];      // hidden-half preacts
__device__ __align__(128) float g_probs[N_ROWS * TOPK];
__device__ __align__(128) float g_zpart[N_ROWS * DTILES];
__device__ __align__(128) float g_rsum[N_ROWS];          // sum of exp(logits)
__device__ __align__(128) float g_C[N_ROWS];             // per-row shift const
__device__ __align__(128) float g_m[N_ROWS];             // mixing weight

// ---------------------------------------------------------------------------
// Fused f32 -> bf16 bulk convert for hidden + mW1 (one launch).
// ---------------------------------------------------------------------------
__global__ __launch_bounds__(256) void conv2_kernel(
    const float* __restrict__ a, __nv_bfloat16* __restrict__ da, int n8a,
    const float* __restrict__ b, __nv_bfloat16* __restrict__ db, int n8b)
{
    const int total = n8a + n8b;
    for (int i = blockIdx.x * 256 + threadIdx.x; i < total; i += gridDim.x * 256) {
        const float* s; __nv_bfloat16* d; int j;
        if (i < n8a) { s = a; d = da; j = i; }
        else         { s = b; d = db; j = i - n8a; }
        float4 f0 = ((const float4*)s)[2 * j];
        float4 f1 = ((const float4*)s)[2 * j + 1];
        __nv_bfloat162 t0 = __floats2bfloat162_rn(f0.x, f0.y);
        __nv_bfloat162 t1 = __floats2bfloat162_rn(f0.z, f0.w);
        __nv_bfloat162 t2 = __floats2bfloat162_rn(f1.x, f1.y);
        __nv_bfloat162 t3 = __floats2bfloat162_rn(f1.z, f1.w);
        uint4 u;
        u.x = *(unsigned*)&t0; u.y = *(unsigned*)&t1;
        u.z = *(unsigned*)&t2; u.w = *(unsigned*)&t3;
        ((uint4*)d)[j] = u;
    }
}

// ---------------------------------------------------------------------------
// Kernel A: per-row prep (unchanged R13).
// ---------------------------------------------------------------------------
__global__ __launch_bounds__(256) void prep_kernel(
    const float* __restrict__ hidden,
    const float* __restrict__ dist,
    const float* __restrict__ sh,
    const float* __restrict__ bW,
    const float* __restrict__ bb)
{
    const int n = blockIdx.x;
    __shared__ __nv_bfloat16 s_sh[TOPK * DIM];   // 32 KB
    __shared__ float s_probs[TOPK];
    __shared__ float sred[8];

    const int tid = threadIdx.x, lane = tid & 31;
    const float4* sh4 = (const float4*)(sh + (size_t)n * (TOPK * DIM));
    const float4* bW4 = (const float4*)bW;

    float acc = 0.f;
    #pragma unroll 4
    for (int i = tid; i < TOPK * DIM / 4; i += 256) {
        float4 v = sh4[i];
        float4 w = __ldg(&bW4[DIM / 4 + (i & (DIM / 4 - 1))]);
        acc += v.x * w.x + v.y * w.y + v.z * w.z + v.w * w.w;
        __nv_bfloat162 p0 = __floats2bfloat162_rn(v.x, v.y);
        __nv_bfloat162 p1 = __floats2bfloat162_rn(v.z, v.w);
        uint2 u; u.x = *(unsigned*)&p0; u.y = *(unsigned*)&p1;
        *(uint2*)(s_sh + 4 * i) = u;
    }
    acc *= (1.f / (float)TOPK);

    {
        float4 v = ((const float4*)(hidden + (size_t)n * DIM))[tid];
        float4 w = __ldg(&bW4[tid]);
        acc += v.x * w.x + v.y * w.y + v.z * w.z + v.w * w.w;
    }

    #pragma unroll
    for (int o = 16; o > 0; o >>= 1)
        acc += __shfl_xor_sync(0xffffffffu, acc, o);
    if (lane == 0) sred[tid >> 5] = acc;
    __syncthreads();

    if (tid < 32) {
        float tot = sred[0] + sred[1] + sred[2] + sred[3]
                  + sred[4] + sred[5] + sred[6] + sred[7];
        float bwv = expf(tot + __ldg(&bb[0]));

        int k = lane & 15;
        float x = -__ldg(&dist[(size_t)n * TOPK + k]) / bwv;
        float mx = x, sm;
        #pragma unroll
        for (int o = 8; o > 0; o >>= 1)
            mx = fmaxf(mx, __shfl_xor_sync(0xffffffffu, mx, o, 16));
        float e = expf(x - mx);
        sm = e;
        #pragma unroll
        for (int o = 8; o > 0; o >>= 1)
            sm += __shfl_xor_sync(0xffffffffu, sm, o, 16);
        float p = e / sm;
        if (lane < 16) {
            s_probs[k] = p;
            g_probs[(size_t)n * TOPK + k] = p;
        }
    }
    __syncthreads();

    {
        const int i = tid;
        float mx_ = 0.f, my_ = 0.f, mz_ = 0.f, mw_ = 0.f;
        #pragma unroll
        for (int k = 0; k < TOPK; k++) {
            float p = s_probs[k];
            uint2 u = *(const uint2*)(s_sh + k * DIM + 4 * i);
            __nv_bfloat162 b0 = *(__nv_bfloat162*)&u.x;
            __nv_bfloat162 b1 = *(__nv_bfloat162*)&u.y;
            float2 f0 = __bfloat1622float2(b0);
            float2 f1 = __bfloat1622float2(b1);
            mx_ = fmaf(p, f0.x, mx_); my_ = fmaf(p, f0.y, my_);
            mz_ = fmaf(p, f1.x, mz_); mw_ = fmaf(p, f1.y, mw_);
        }
        __nv_bfloat162 p0 = __floats2bfloat162_rn(mx_, my_);
        __nv_bfloat162 p1 = __floats2bfloat162_rn(mz_, mw_);
        uint2 u; u.x = *(unsigned*)&p0; u.y = *(unsigned*)&p1;
        *(uint2*)(g_merged_h + (size_t)n * DIM + 4 * i) = u;
    }
}

// ---------------------------------------------------------------------------
// Kernel B: half-GEMM, bf16 HMMA, 3-stage cp.async pipeline (unchanged R13).
// ---------------------------------------------------------------------------
#define GP 72
#define GSTAGE (128 * GP)
#define GEMM_SMEM (3 * 2 * GSTAGE * 2)    // 110592 B
#define NCH 16

__device__ __forceinline__ void cp16(uint32_t saddr, const void* g) {
    asm volatile("cp.async.cg.shared.global [%0], [%1], 16;"
                 :: "r"(saddr), "l"(__cvta_generic_to_global(g)));
}

__global__ __launch_bounds__(256, 1) void gemm_kernel(
    const __nv_bfloat16* __restrict__ Ah,
    const float* __restrict__ mb1,
    const float* __restrict__ mW2,
    int kbase, int phase)
{
    extern __shared__ __align__(16) char smem_raw[];
    __nv_bfloat16* smem_h = (__nv_bfloat16*)smem_raw;
    uint32_t sbase;
    asm("{ .reg .u64 t; cvta.to.shared.u64 t, %1; cvt.u32.u64 %0, t; }"
        : "=r"(sbase) : "l"(smem_raw));

    const int tid  = threadIdx.x;
    const int wid  = tid >> 5, lane = tid & 31;
    const int rowTile = blockIdx.x;
    const int dTile   = blockIdx.y;
    const int warpM = wid >> 2;
    const int warpN = wid & 3;

    wmma::fragment<wmma::accumulator, 16, 16, 16, float> c[4][2];
    #pragma unroll
    for (int mi = 0; mi < 4; mi++)
        #pragma unroll
        for (int ni = 0; ni < 2; ni++)
            wmma::fill_fragment(c[mi][ni], 0.f);

    const __nv_bfloat16* Bh = g_mW1_h;

    auto issue = [&](int it) {
        const int buf = it % 3;
        const uint32_t sA = sbase + buf * 2 * GSTAGE * 2;
        const uint32_t sB = sA + GSTAGE * 2;
        #pragma unroll
        for (int j = 0; j < 4; j++) {
            int idx = tid + 256 * j;
            int row = idx >> 3, qc = idx & 7;
            cp16(sA + (row * GP + qc * 8) * 2,
                 Ah + (size_t)(rowTile * 128 + row) * DIM + it * 64 + qc * 8);
            cp16(sB + (row * GP + qc * 8) * 2,
                 Bh + (size_t)(dTile * 128 + row) * KTOT + kbase + it * 64 + qc * 8);
        }
        asm volatile("cp.async.commit_group;" ::: "memory");
    };

    issue(0);
    issue(1);
    for (int it = 0; it < NCH; ++it) {
        if (it + 1 < NCH)
            asm volatile("cp.async.wait_group 1;" ::: "memory");
        else
            asm volatile("cp.async.wait_group 0;" ::: "memory");
        __syncthreads();

        const __nv_bfloat16* As = smem_h + (it % 3) * 2 * GSTAGE;
        const __nv_bfloat16* Bs = As + GSTAGE;
        #pragma unroll
        for (int kk = 0; kk < 4; kk++) {
            wmma::fragment<wmma::matrix_a, 16, 16, 16, __nv_bfloat16, wmma::row_major> a[4];
            wmma::fragment<wmma::matrix_b, 16, 16, 16, __nv_bfloat16, wmma::col_major> b[2];
            #pragma unroll
            for (int mi = 0; mi < 4; mi++)
                wmma::load_matrix_sync(a[mi], As + (warpM * 64 + mi * 16) * GP + kk * 16, GP);
            #pragma unroll
            for (int ni = 0; ni < 2; ni++)
                wmma::load_matrix_sync(b[ni], Bs + (warpN * 32 + ni * 16) * GP + kk * 16, GP);
            #pragma unroll
            for (int mi = 0; mi < 4; mi++)
                #pragma unroll
                for (int ni = 0; ni < 2; ni++)
                    wmma::mma_sync(c[mi][ni], a[mi], b[ni], c[mi][ni]);
        }
        if (it + 2 < NCH) issue(it + 2);
    }
    __syncthreads();

    float* fbuf  = (float*)smem_raw;
    float* scr   = fbuf + wid * 320;
    float* zrows = fbuf + 8 * 320;
    const int r16 = lane & 15, half = lane >> 4;

    if (phase == 0) {
        #pragma unroll
        for (int mi = 0; mi < 4; mi++) {
            #pragma unroll
            for (int ni = 0; ni < 2; ni++) {
                wmma::store_matrix_sync(scr, c[mi][ni], 20, wmma::mem_row_major);
                __syncwarp();
                int grow = rowTile * 128 + warpM * 64 + mi * 16 + r16;
                int gcol = dTile * 128 + warpN * 32 + ni * 16 + half * 8;
                *(float4*)(g_ch + (size_t)grow * DIM + gcol) =
                    *(float4*)(scr + r16 * 20 + half * 8);
                *(float4*)(g_ch + (size_t)grow * DIM + gcol + 4) =
                    *(float4*)(scr + r16 * 20 + half * 8 + 4);
                __syncwarp();
            }
        }
    } else {
        float zacc[4] = {0.f, 0.f, 0.f, 0.f};
        #pragma unroll
        for (int mi = 0; mi < 4; mi++) {
            #pragma unroll
            for (int ni = 0; ni < 2; ni++) {
                wmma::store_matrix_sync(scr, c[mi][ni], 20, wmma::mem_row_major);
                __syncwarp();
                int grow = rowTile * 128 + warpM * 64 + mi * 16 + r16;
                int gc0  = dTile * 128 + warpN * 32 + ni * 16 + half * 8;
                const float* chs = g_ch + (size_t)grow * DIM + gc0;
                float z = 0.f;
                #pragma unroll
                for (int cc = 0; cc < 8; cc++) {
                    float v = scr[r16 * 20 + half * 8 + cc] + chs[cc] + __ldg(&mb1[gc0 + cc]);
                    z = fmaf(fmaxf(v, 0.f), __ldg(&mW2[gc0 + cc]), z);
                }
                z += __shfl_xor_sync(0xffffffffu, z, 16);
                zacc[mi] += z;
                __syncwarp();
            }
        }
        if (lane < 16) {
            #pragma unroll
            for (int mi = 0; mi < 4; mi++)
                zrows[(warpM * 64 + mi * 16 + lane) * 4 + warpN] = zacc[mi];
        }
        __syncthreads();
        if (tid < 128) {
            float zz = zrows[tid * 4 + 0] + zrows[tid * 4 + 1]
                     + zrows[tid * 4 + 2] + zrows[tid * 4 + 3];
            g_zpart[(size_t)(rowTile * 128 + tid) * DTILES + dTile] = zz;
        }
    }
}

// ---------------------------------------------------------------------------
// Kernel C1: per-row SUM of exp(logits). Loads are 32B L2::evict_last
// (.v4.u64 — the only legal width for the modifier on this target) so the
// tail's .cs traffic leaves them resident for re-read.
// ---------------------------------------------------------------------------
__device__ __forceinline__ void ldel8(const float* p, float4& a, float4& b) {
    unsigned long long r0, r1, r2, r3;
    asm volatile("ld.global.L2::evict_last.v4.u64 {%0,%1,%2,%3}, [%4];"
                 : "=l"(r0), "=l"(r1), "=l"(r2), "=l"(r3)
                 : "l"(__cvta_generic_to_global(p)));
    a.x = __uint_as_float((unsigned)(r0));
    a.y = __uint_as_float((unsigned)(r0 >> 32));
    a.z = __uint_as_float((unsigned)(r1));
    a.w = __uint_as_float((unsigned)(r1 >> 32));
    b.x = __uint_as_float((unsigned)(r2));
    b.y = __uint_as_float((unsigned)(r2 >> 32));
    b.z = __uint_as_float((unsigned)(r3));
    b.w = __uint_as_float((unsigned)(r3 >> 32));
}

__global__ __launch_bounds__(256) void stat_kernel(
    const float* __restrict__ logits, int nbase)
{
    const int n = nbase + blockIdx.x;
    const int tid = threadIdx.x, lane = tid & 31, wid = tid >> 5;
    __shared__ float ss_[8];

    const float* lrow = logits + (size_t)n * VOCAB;
    float ax = 0.f, ay = 0.f, az = 0.f, aw = 0.f;
    #pragma unroll 2
    for (int i = tid; i < VOCAB / 8; i += 256) {   // 4000 chunks of 8 floats
        float4 a, b;
        ldel8(lrow + 8 * i, a, b);
        ax += expf(a.x) + expf(b.x);
        ay += expf(a.y) + expf(b.y);
        az += expf(a.z) + expf(b.z);
        aw += expf(a.w) + expf(b.w);
    }
    float s = (ax + ay) + (az + aw);
    #pragma unroll
    for (int o = 16; o > 0; o >>= 1)
        s += __shfl_xor_sync(0xffffffffu, s, o);
    if (lane == 0) ss_[wid] = s;
    __syncthreads();
    if (tid == 0) {
        float S = 0.f;
        #pragma unroll
        for (int i = 0; i < 8; i++) S += ss_[i];
        g_rsum[n] = S;
    }
}

// ---------------------------------------------------------------------------
// Kernel Z: per-row mixing weight + shift constant, row-half split.
// ---------------------------------------------------------------------------
__global__ __launch_bounds__(256) void zfin_kernel(
    const float* __restrict__ mb2, int nbase)
{
    const int n = nbase + blockIdx.x * 256 + threadIdx.x;  // grid 4 x 256
    float z = __ldg(&mb2[0]);
    #pragma unroll
    for (int j = 0; j < DTILES; j++) z += g_zpart[(size_t)n * DTILES + j];
    float m = 1.f / (1.f + expf(-z));
    g_m[n] = m;
    g_C[n] = logf(g_rsum[n]) - logf(1.f - m);       // out = lg - C
}

// ---------------------------------------------------------------------------
// Kernel C2: pure-stream write (evict-first), quarter-row blocks, half split.
// ---------------------------------------------------------------------------
__device__ __forceinline__ float4 ldcs4(const float4* p) {
    float4 v;
    asm volatile("ld.global.cs.v4.f32 {%0,%1,%2,%3}, [%4];"
                 : "=f"(v.x), "=f"(v.y), "=f"(v.z), "=f"(v.w)
                 : "l"(__cvta_generic_to_global(p)));
    return v;
}
__device__ __forceinline__ void stcs4(float4* p, float4 v) {
    asm volatile("st.global.cs.v4.f32 [%0], {%1,%2,%3,%4};"
                 :: "l"(__cvta_generic_to_global(p)),
                    "f"(v.x), "f"(v.y), "f"(v.z), "f"(v.w));
}

#define WSEG 2000   // float4 per quarter row (8000/4)

__global__ __launch_bounds__(256) void write_kernel(
    const float* __restrict__ logits, float* __restrict__ out, int nbase)
{
    const int n   = nbase + (blockIdx.x >> 2);
    const int seg = blockIdx.x & 3;
    const float C = __ldg(&g_C[n]);

    const float4* l4 = (const float4*)(logits + (size_t)n * VOCAB) + seg * WSEG;
    float4*       o4 = (float4*)(out + (size_t)n * VOCAB) + seg * WSEG;
    #pragma unroll 4
    for (int i = threadIdx.x; i < WSEG; i += 256) {
        float4 v = ldcs4(l4 + i);
        v.x -= C; v.y -= C; v.z -= C; v.w -= C;
        stcs4(o4 + i, v);
    }
}

// ---------------------------------------------------------------------------
// Kernel F: scatter fixups, one warp per row, row-half split.
// ---------------------------------------------------------------------------
__global__ __launch_bounds__(32) void fixup_kernel(
    const float* __restrict__ logits,
    const void* __restrict__ tok,
    float* __restrict__ out, int nbase)
{
    const int n = nbase + blockIdx.x;
    const int lane = threadIdx.x;

    const int* t32 = (const int*)tok;
    int is64 = 1;
    #pragma unroll
    for (int k = 0; k < TOPK; k++)
        if (t32[2 * k + 1] != 0) is64 = 0;

    const int k = lane & 15;
    int idx;
    if (is64) idx = (int)((const long long*)tok)[(size_t)n * TOPK + k];
    else      idx = t32[(size_t)n * TOPK + k];
    idx = min(max(idx, 0), VOCAB - 1);

    float m = __ldg(&g_m[n]);
    float val = m * __ldg(&g_probs[(size_t)n * TOPK + k]);

    if (lane < 16) {
        bool first = true;
        float tot = 0.f;
        #pragma unroll
        for (int j = 0; j < 16; j++) {
            int   ij = __shfl_sync(0x0000ffffu, idx, j, 16);
            float vj = __shfl_sync(0x0000ffffu, val, j, 16);
            if (ij == idx) {
                if (j < k) first = false;
                tot += vj;
            }
        }
        if (first) {
            float lg = __ldg(&logits[(size_t)n * VOCAB + idx]);
            float p = expf(lg) / __ldg(&g_rsum[n]);
            out[(size_t)n * VOCAB + idx] = logf((1.f - m) * p + tot);
        }
    }
}

// ---------------------------------------------------------------------------
// Host: R13 fork-join topology exactly (2 streams, 4 events).
// ---------------------------------------------------------------------------
extern "C" void kernel_launch(void* const* d_in, const int* in_sizes, int n_in,
                              void* d_out, int out_size)
{
    int i_logits = -1, i_sh = -1, i_bW = -1;
    int p2m[2] = {-1, -1};  int n2m = 0;
    int p32k[2] = {-1, -1}; int n32k = 0;
    int p1k[2] = {-1, -1};  int n1k = 0;
    int p1[2] = {-1, -1};   int n1 = 0;

    for (int i = 0; i < n_in; i++) {
        switch (in_sizes[i]) {
            case 65536000: i_logits = i; break;
            case 33554432: i_sh = i; break;
            case 2048:     i_bW = i; break;
            case 2097152:  if (n2m < 2) p2m[n2m++] = i; break;
            case 32768:    if (n32k < 2) p32k[n32k++] = i; break;
            case 1024:     if (n1k < 2) p1k[n1k++] = i; break;
            case 1:        if (n1 < 2) p1[n1++] = i; break;
            default: break;
        }
    }
    const bool alpha = (i_bW >= 0 && i_logits >= 0 && i_bW < i_logits);
    const int i_hidden = p2m[0],  i_mW1 = p2m[1];
    const int i_dist   = p32k[0], i_tok = p32k[1];
    const int i_bb     = p1[0],   i_mb2 = p1[1];
    const int i_mb1    = alpha ? p1k[1] : p1k[0];
    const int i_mW2    = alpha ? p1k[0] : p1k[1];

    const float* hidden = (const float*)d_in[i_hidden];
    const float* logits = (const float*)d_in[i_logits];
    const float* dist   = (const float*)d_in[i_dist];
    const float* sh     = (const float*)d_in[i_sh];
    const void*  tok    = d_in[i_tok];
    const float* bW     = (const float*)d_in[i_bW];
    const float* bb     = (const float*)d_in[i_bb];
    const float* mW1    = (const float*)d_in[i_mW1];
    const float* mb1    = (const float*)d_in[i_mb1];
    const float* mW2    = (const float*)d_in[i_mW2];
    const float* mb2    = (const float*)d_in[i_mb2];
    float*       out    = (float*)d_out;

    __nv_bfloat16 *hidden_h = nullptr, *mW1_h = nullptr, *merged_h = nullptr;
    cudaGetSymbolAddress((void**)&hidden_h, g_hidden_h);
    cudaGetSymbolAddress((void**)&mW1_h,   g_mW1_h);
    cudaGetSymbolAddress((void**)&merged_h, g_merged_h);

    cudaFuncSetAttribute(gemm_kernel, cudaFuncAttributeMaxDynamicSharedMemorySize, GEMM_SMEM);

    cudaStream_t s2;
    cudaStreamCreateWithFlags(&s2, cudaStreamNonBlocking);
    cudaEvent_t e0, e1, eSL, e2;
    cudaEventCreateWithFlags(&e0,  cudaEventDisableTiming);
    cudaEventCreateWithFlags(&e1,  cudaEventDisableTiming);
    cudaEventCreateWithFlags(&eSL, cudaEventDisableTiming);
    cudaEventCreateWithFlags(&e2,  cudaEventDisableTiming);

    cudaEventRecord(e0, 0);
    cudaStreamWaitEvent(s2, e0, 0);

    // S2: fused convert -> gemm0 -> (e1) gemm1 -> (eSL) low-half output tail.
    conv2_kernel<<<768, 256, 0, s2>>>(hidden, hidden_h, N_ROWS * DIM / 8,
                                      mW1, mW1_h, DIM * KTOT / 8);
    gemm_kernel<<<dim3(16, 8), 256, GEMM_SMEM, s2>>>(hidden_h, mb1, mW2, 0, 0);

    // Origin: prep -> (e1) -> stat_lo -> (eSL) -> stat_hi -> (e2) hi-half tail.
    prep_kernel<<<N_ROWS, 256>>>(hidden, dist, sh, bW, bb);
    cudaEventRecord(e1, 0);
    stat_kernel<<<HALF_ROWS, 256>>>(logits, 0);
    cudaEventRecord(eSL, 0);
    stat_kernel<<<HALF_ROWS, 256>>>(logits, HALF_ROWS);

    // S2: merged-half GEMM after prep, then low-half write pipeline.
    cudaStreamWaitEvent(s2, e1, 0);
    gemm_kernel<<<dim3(16, 8), 256, GEMM_SMEM, s2>>>(merged_h, mb1, mW2, DIM, 1);
    cudaEventRecord(e2, s2);
    cudaStreamWaitEvent(s2, eSL, 0);
    zfin_kernel<<<HALF_ROWS / 256, 256, 0, s2>>>(mb2, 0);
    write_kernel<<<HALF_ROWS * 4, 256, 0, s2>>>(logits, out, 0);
    fixup_kernel<<<HALF_ROWS, 32, 0, s2>>>(logits, tok, out, 0);

    // Origin: high-half write pipeline after gemm1.
    cudaStreamWaitEvent(0, e2, 0);
    zfin_kernel<<<HALF_ROWS / 256, 256>>>(mb2, HALF_ROWS);
    write_kernel<<<HALF_ROWS * 4, 256>>>(logits, out, HALF_ROWS);
    fixup_kernel<<<HALF_ROWS, 32>>>(logits, tok, out, HALF_ROWS);

    // Join: origin must also wait for s2's low-half tail before returning.
    cudaEventRecord(e0, s2);            // reuse e0 as s2-done marker
    cudaStreamWaitEvent(0, e0, 0);
}

// round 17
// speedup vs baseline: 1.1056x; 1.0105x over previous
#include <cuda_runtime.h>
#include <cuda_bf16.h>
#include <mma.h>
#include <math.h>
#include <stdint.h>

using namespace nvcuda;

// Problem constants (B=2, S=1024, D=1024, V=32000, K=16)
#define N_ROWS 2048
#define DIM    1024
#define VOCAB  32000
#define TOPK   16
#define KTOT   2048   // 2*DIM
#define DTILES 8      // DIM/128
#define HALF_ROWS (N_ROWS / 2)

// Scratch (device globals; no allocation allowed)
__device__ __align__(128) __nv_bfloat16 g_merged_h[N_ROWS * DIM];
__device__ __align__(128) __nv_bfloat16 g_hidden_h[N_ROWS * DIM];
__device__ __align__(128) __nv_bfloat16 g_mW1_h[DIM * KTOT];
__device__ __align__(128) float g_ch[N_ROWS * DIM];      // hidden-half preacts
__device__ __align__(128) float g_probs[N_ROWS * TOPK];
__device__ __align__(128) float g_zpart[N_ROWS * DTILES];
__device__ __align__(128) float g_rsum[N_ROWS];          // sum of exp(logits)
__device__ __align__(128) float g_C[N_ROWS];             // per-row shift const
__device__ __align__(128) float g_m[N_ROWS];             // mixing weight

// ---------------------------------------------------------------------------
// Fused f32 -> bf16 bulk convert for hidden + mW1 (one launch).
// ---------------------------------------------------------------------------
__global__ __launch_bounds__(256) void conv2_kernel(
    const float* __restrict__ a, __nv_bfloat16* __restrict__ da, int n8a,
    const float* __restrict__ b, __nv_bfloat16* __restrict__ db, int n8b)
{
    const int total = n8a + n8b;
    for (int i = blockIdx.x * 256 + threadIdx.x; i < total; i += gridDim.x * 256) {
        const float* s; __nv_bfloat16* d; int j;
        if (i < n8a) { s = a; d = da; j = i; }
        else         { s = b; d = db; j = i - n8a; }
        float4 f0 = ((const float4*)s)[2 * j];
        float4 f1 = ((const float4*)s)[2 * j + 1];
        __nv_bfloat162 t0 = __floats2bfloat162_rn(f0.x, f0.y);
        __nv_bfloat162 t1 = __floats2bfloat162_rn(f0.z, f0.w);
        __nv_bfloat162 t2 = __floats2bfloat162_rn(f1.x, f1.y);
        __nv_bfloat162 t3 = __floats2bfloat162_rn(f1.z, f1.w);
        uint4 u;
        u.x = *(unsigned*)&t0; u.y = *(unsigned*)&t1;
        u.z = *(unsigned*)&t2; u.w = *(unsigned*)&t3;
        ((uint4*)d)[j] = u;
    }
}

// ---------------------------------------------------------------------------
// Kernel A: per-row prep (unchanged).
// ---------------------------------------------------------------------------
__global__ __launch_bounds__(256) void prep_kernel(
    const float* __restrict__ hidden,
    const float* __restrict__ dist,
    const float* __restrict__ sh,
    const float* __restrict__ bW,
    const float* __restrict__ bb)
{
    const int n = blockIdx.x;
    __shared__ __nv_bfloat16 s_sh[TOPK * DIM];   // 32 KB
    __shared__ float s_probs[TOPK];
    __shared__ float sred[8];

    const int tid = threadIdx.x, lane = tid & 31;
    const float4* sh4 = (const float4*)(sh + (size_t)n * (TOPK * DIM));
    const float4* bW4 = (const float4*)bW;

    float acc = 0.f;
    #pragma unroll 4
    for (int i = tid; i < TOPK * DIM / 4; i += 256) {
        float4 v = sh4[i];
        float4 w = __ldg(&bW4[DIM / 4 + (i & (DIM / 4 - 1))]);
        acc += v.x * w.x + v.y * w.y + v.z * w.z + v.w * w.w;
        __nv_bfloat162 p0 = __floats2bfloat162_rn(v.x, v.y);
        __nv_bfloat162 p1 = __floats2bfloat162_rn(v.z, v.w);
        uint2 u; u.x = *(unsigned*)&p0; u.y = *(unsigned*)&p1;
        *(uint2*)(s_sh + 4 * i) = u;
    }
    acc *= (1.f / (float)TOPK);

    {
        float4 v = ((const float4*)(hidden + (size_t)n * DIM))[tid];
        float4 w = __ldg(&bW4[tid]);
        acc += v.x * w.x + v.y * w.y + v.z * w.z + v.w * w.w;
    }

    #pragma unroll
    for (int o = 16; o > 0; o >>= 1)
        acc += __shfl_xor_sync(0xffffffffu, acc, o);
    if (lane == 0) sred[tid >> 5] = acc;
    __syncthreads();

    if (tid < 32) {
        float tot = sred[0] + sred[1] + sred[2] + sred[3]
                  + sred[4] + sred[5] + sred[6] + sred[7];
        float bwv = expf(tot + __ldg(&bb[0]));

        int k = lane & 15;
        float x = -__ldg(&dist[(size_t)n * TOPK + k]) / bwv;
        float mx = x, sm;
        #pragma unroll
        for (int o = 8; o > 0; o >>= 1)
            mx = fmaxf(mx, __shfl_xor_sync(0xffffffffu, mx, o, 16));
        float e = expf(x - mx);
        sm = e;
        #pragma unroll
        for (int o = 8; o > 0; o >>= 1)
            sm += __shfl_xor_sync(0xffffffffu, sm, o, 16);
        float p = e / sm;
        if (lane < 16) {
            s_probs[k] = p;
            g_probs[(size_t)n * TOPK + k] = p;
        }
    }
    __syncthreads();

    {
        const int i = tid;
        float mx_ = 0.f, my_ = 0.f, mz_ = 0.f, mw_ = 0.f;
        #pragma unroll
        for (int k = 0; k < TOPK; k++) {
            float p = s_probs[k];
            uint2 u = *(const uint2*)(s_sh + k * DIM + 4 * i);
            __nv_bfloat162 b0 = *(__nv_bfloat162*)&u.x;
            __nv_bfloat162 b1 = *(__nv_bfloat162*)&u.y;
            float2 f0 = __bfloat1622float2(b0);
            float2 f1 = __bfloat1622float2(b1);
            mx_ = fmaf(p, f0.x, mx_); my_ = fmaf(p, f0.y, my_);
            mz_ = fmaf(p, f1.x, mz_); mw_ = fmaf(p, f1.y, mw_);
        }
        __nv_bfloat162 p0 = __floats2bfloat162_rn(mx_, my_);
        __nv_bfloat162 p1 = __floats2bfloat162_rn(mz_, mw_);
        uint2 u; u.x = *(unsigned*)&p0; u.y = *(unsigned*)&p1;
        *(uint2*)(g_merged_h + (size_t)n * DIM + 4 * i) = u;
    }
}

// ---------------------------------------------------------------------------
// Kernel B: half-GEMM, bf16 HMMA, 3-stage cp.async pipeline (unchanged).
// ---------------------------------------------------------------------------
#define GP 72
#define GSTAGE (128 * GP)
#define GEMM_SMEM (3 * 2 * GSTAGE * 2)    // 110592 B
#define NCH 16

__device__ __forceinline__ void cp16(uint32_t saddr, const void* g) {
    asm volatile("cp.async.cg.shared.global [%0], [%1], 16;"
                 :: "r"(saddr), "l"(__cvta_generic_to_global(g)));
}

__global__ __launch_bounds__(256, 1) void gemm_kernel(
    const __nv_bfloat16* __restrict__ Ah,
    const float* __restrict__ mb1,
    const float* __restrict__ mW2,
    int kbase, int phase)
{
    extern __shared__ __align__(16) char smem_raw[];
    __nv_bfloat16* smem_h = (__nv_bfloat16*)smem_raw;
    uint32_t sbase;
    asm("{ .reg .u64 t; cvta.to.shared.u64 t, %1; cvt.u32.u64 %0, t; }"
        : "=r"(sbase) : "l"(smem_raw));

    const int tid  = threadIdx.x;
    const int wid  = tid >> 5, lane = tid & 31;
    const int rowTile = blockIdx.x;
    const int dTile   = blockIdx.y;
    const int warpM = wid >> 2;
    const int warpN = wid & 3;

    wmma::fragment<wmma::accumulator, 16, 16, 16, float> c[4][2];
    #pragma unroll
    for (int mi = 0; mi < 4; mi++)
        #pragma unroll
        for (int ni = 0; ni < 2; ni++)
            wmma::fill_fragment(c[mi][ni], 0.f);

    const __nv_bfloat16* Bh = g_mW1_h;

    auto issue = [&](int it) {
        const int buf = it % 3;
        const uint32_t sA = sbase + buf * 2 * GSTAGE * 2;
        const uint32_t sB = sA + GSTAGE * 2;
        #pragma unroll
        for (int j = 0; j < 4; j++) {
            int idx = tid + 256 * j;
            int row = idx >> 3, qc = idx & 7;
            cp16(sA + (row * GP + qc * 8) * 2,
                 Ah + (size_t)(rowTile * 128 + row) * DIM + it * 64 + qc * 8);
            cp16(sB + (row * GP + qc * 8) * 2,
                 Bh + (size_t)(dTile * 128 + row) * KTOT + kbase + it * 64 + qc * 8);
        }
        asm volatile("cp.async.commit_group;" ::: "memory");
    };

    issue(0);
    issue(1);
    for (int it = 0; it < NCH; ++it) {
        if (it + 1 < NCH)
            asm volatile("cp.async.wait_group 1;" ::: "memory");
        else
            asm volatile("cp.async.wait_group 0;" ::: "memory");
        __syncthreads();

        const __nv_bfloat16* As = smem_h + (it % 3) * 2 * GSTAGE;
        const __nv_bfloat16* Bs = As + GSTAGE;
        #pragma unroll
        for (int kk = 0; kk < 4; kk++) {
            wmma::fragment<wmma::matrix_a, 16, 16, 16, __nv_bfloat16, wmma::row_major> a[4];
            wmma::fragment<wmma::matrix_b, 16, 16, 16, __nv_bfloat16, wmma::col_major> b[2];
            #pragma unroll
            for (int mi = 0; mi < 4; mi++)
                wmma::load_matrix_sync(a[mi], As + (warpM * 64 + mi * 16) * GP + kk * 16, GP);
            #pragma unroll
            for (int ni = 0; ni < 2; ni++)
                wmma::load_matrix_sync(b[ni], Bs + (warpN * 32 + ni * 16) * GP + kk * 16, GP);
            #pragma unroll
            for (int mi = 0; mi < 4; mi++)
                #pragma unroll
                for (int ni = 0; ni < 2; ni++)
                    wmma::mma_sync(c[mi][ni], a[mi], b[ni], c[mi][ni]);
        }
        if (it + 2 < NCH) issue(it + 2);
    }
    __syncthreads();

    float* fbuf  = (float*)smem_raw;
    float* scr   = fbuf + wid * 320;
    float* zrows = fbuf + 8 * 320;
    const int r16 = lane & 15, half = lane >> 4;

    if (phase == 0) {
        #pragma unroll
        for (int mi = 0; mi < 4; mi++) {
            #pragma unroll
            for (int ni = 0; ni < 2; ni++) {
                wmma::store_matrix_sync(scr, c[mi][ni], 20, wmma::mem_row_major);
                __syncwarp();
                int grow = rowTile * 128 + warpM * 64 + mi * 16 + r16;
                int gcol = dTile * 128 + warpN * 32 + ni * 16 + half * 8;
                *(float4*)(g_ch + (size_t)grow * DIM + gcol) =
                    *(float4*)(scr + r16 * 20 + half * 8);
                *(float4*)(g_ch + (size_t)grow * DIM + gcol + 4) =
                    *(float4*)(scr + r16 * 20 + half * 8 + 4);
                __syncwarp();
            }
        }
    } else {
        float zacc[4] = {0.f, 0.f, 0.f, 0.f};
        #pragma unroll
        for (int mi = 0; mi < 4; mi++) {
            #pragma unroll
            for (int ni = 0; ni < 2; ni++) {
                wmma::store_matrix_sync(scr, c[mi][ni], 20, wmma::mem_row_major);
                __syncwarp();
                int grow = rowTile * 128 + warpM * 64 + mi * 16 + r16;
                int gc0  = dTile * 128 + warpN * 32 + ni * 16 + half * 8;
                const float* chs = g_ch + (size_t)grow * DIM + gc0;
                float z = 0.f;
                #pragma unroll
                for (int cc = 0; cc < 8; cc++) {
                    float v = scr[r16 * 20 + half * 8 + cc] + chs[cc] + __ldg(&mb1[gc0 + cc]);
                    z = fmaf(fmaxf(v, 0.f), __ldg(&mW2[gc0 + cc]), z);
                }
                z += __shfl_xor_sync(0xffffffffu, z, 16);
                zacc[mi] += z;
                __syncwarp();
            }
        }
        if (lane < 16) {
            #pragma unroll
            for (int mi = 0; mi < 4; mi++)
                zrows[(warpM * 64 + mi * 16 + lane) * 4 + warpN] = zacc[mi];
        }
        __syncthreads();
        if (tid < 128) {
            float zz = zrows[tid * 4 + 0] + zrows[tid * 4 + 1]
                     + zrows[tid * 4 + 2] + zrows[tid * 4 + 3];
            g_zpart[(size_t)(rowTile * 128 + tid) * DTILES + dTile] = zz;
        }
    }
}

// ---------------------------------------------------------------------------
// Kernel C1: per-row SUM of exp(logits). Plain 256-bit loads (no L2 hint —
// twice-falsified) + fast __expf (kills the 21% FMA overhead seen in ncu).
// ---------------------------------------------------------------------------
__device__ __forceinline__ void ld8(const float* p, float4& a, float4& b) {
    unsigned long long r0, r1, r2, r3;
    asm volatile("ld.global.v4.u64 {%0,%1,%2,%3}, [%4];"
                 : "=l"(r0), "=l"(r1), "=l"(r2), "=l"(r3)
                 : "l"(__cvta_generic_to_global(p)));
    a.x = __uint_as_float((unsigned)(r0));
    a.y = __uint_as_float((unsigned)(r0 >> 32));
    a.z = __uint_as_float((unsigned)(r1));
    a.w = __uint_as_float((unsigned)(r1 >> 32));
    b.x = __uint_as_float((unsigned)(r2));
    b.y = __uint_as_float((unsigned)(r2 >> 32));
    b.z = __uint_as_float((unsigned)(r3));
    b.w = __uint_as_float((unsigned)(r3 >> 32));
}

__global__ __launch_bounds__(256) void stat_kernel(
    const float* __restrict__ logits, int nbase)
{
    const int n = nbase + blockIdx.x;
    const int tid = threadIdx.x, lane = tid & 31, wid = tid >> 5;
    __shared__ float ss_[8];

    const float* lrow = logits + (size_t)n * VOCAB;
    float ax = 0.f, ay = 0.f, az = 0.f, aw = 0.f;
    #pragma unroll 2
    for (int i = tid; i < VOCAB / 8; i += 256) {   // 4000 chunks of 8 floats
        float4 a, b;
        ld8(lrow + 8 * i, a, b);
        ax += __expf(a.x) + __expf(b.x);
        ay += __expf(a.y) + __expf(b.y);
        az += __expf(a.z) + __expf(b.z);
        aw += __expf(a.w) + __expf(b.w);
    }
    float s = (ax + ay) + (az + aw);
    #pragma unroll
    for (int o = 16; o > 0; o >>= 1)
        s += __shfl_xor_sync(0xffffffffu, s, o);
    if (lane == 0) ss_[wid] = s;
    __syncthreads();
    if (tid == 0) {
        float S = 0.f;
        #pragma unroll
        for (int i = 0; i < 8; i++) S += ss_[i];
        g_rsum[n] = S;
    }
}

// ---------------------------------------------------------------------------
// Kernel Z: per-row mixing weight + shift constant, row-half split.
// ---------------------------------------------------------------------------
__global__ __launch_bounds__(256) void zfin_kernel(
    const float* __restrict__ mb2, int nbase)
{
    const int n = nbase + blockIdx.x * 256 + threadIdx.x;  // grid 4 x 256
    float z = __ldg(&mb2[0]);
    #pragma unroll
    for (int j = 0; j < DTILES; j++) z += g_zpart[(size_t)n * DTILES + j];
    float m = 1.f / (1.f + expf(-z));
    g_m[n] = m;
    g_C[n] = logf(g_rsum[n]) - logf(1.f - m);       // out = lg - C
}

// ---------------------------------------------------------------------------
// Kernel C2: pure-stream write (evict-first), quarter-row blocks, half split.
// ---------------------------------------------------------------------------
__device__ __forceinline__ float4 ldcs4(const float4* p) {
    float4 v;
    asm volatile("ld.global.cs.v4.f32 {%0,%1,%2,%3}, [%4];"
                 : "=f"(v.x), "=f"(v.y), "=f"(v.z), "=f"(v.w)
                 : "l"(__cvta_generic_to_global(p)));
    return v;
}
__device__ __forceinline__ void stcs4(float4* p, float4 v) {
    asm volatile("st.global.cs.v4.f32 [%0], {%1,%2,%3,%4};"
                 :: "l"(__cvta_generic_to_global(p)),
                    "f"(v.x), "f"(v.y), "f"(v.z), "f"(v.w));
}

#define WSEG 2000   // float4 per quarter row (8000/4)

__global__ __launch_bounds__(256) void write_kernel(
    const float* __restrict__ logits, float* __restrict__ out, int nbase)
{
    const int n   = nbase + (blockIdx.x >> 2);
    const int seg = blockIdx.x & 3;
    const float C = __ldg(&g_C[n]);

    const float4* l4 = (const float4*)(logits + (size_t)n * VOCAB) + seg * WSEG;
    float4*       o4 = (float4*)(out + (size_t)n * VOCAB) + seg * WSEG;
    #pragma unroll 4
    for (int i = threadIdx.x; i < WSEG; i += 256) {
        float4 v = ldcs4(l4 + i);
        v.x -= C; v.y -= C; v.z -= C; v.w -= C;
        stcs4(o4 + i, v);
    }
}

// ---------------------------------------------------------------------------
// Kernel F: scatter fixups, one warp per row, row-half split.
// ---------------------------------------------------------------------------
__global__ __launch_bounds__(32) void fixup_kernel(
    const float* __restrict__ logits,
    const void* __restrict__ tok,
    float* __restrict__ out, int nbase)
{
    const int n = nbase + blockIdx.x;
    const int lane = threadIdx.x;

    const int* t32 = (const int*)tok;
    int is64 = 1;
    #pragma unroll
    for (int k = 0; k < TOPK; k++)
        if (t32[2 * k + 1] != 0) is64 = 0;

    const int k = lane & 15;
    int idx;
    if (is64) idx = (int)((const long long*)tok)[(size_t)n * TOPK + k];
    else      idx = t32[(size_t)n * TOPK + k];
    idx = min(max(idx, 0), VOCAB - 1);

    float m = __ldg(&g_m[n]);
    float val = m * __ldg(&g_probs[(size_t)n * TOPK + k]);

    if (lane < 16) {
        bool first = true;
        float tot = 0.f;
        #pragma unroll
        for (int j = 0; j < 16; j++) {
            int   ij = __shfl_sync(0x0000ffffu, idx, j, 16);
            float vj = __shfl_sync(0x0000ffffu, val, j, 16);
            if (ij == idx) {
                if (j < k) first = false;
                tot += vj;
            }
        }
        if (first) {
            float lg = __ldg(&logits[(size_t)n * VOCAB + idx]);
            float p = expf(lg) / __ldg(&g_rsum[n]);
            out[(size_t)n * VOCAB + idx] = logf((1.f - m) * p + tot);
        }
    }
}

// ---------------------------------------------------------------------------
// Host: R13/R16 fork-join topology exactly (2 streams, 4 events).
// ---------------------------------------------------------------------------
extern "C" void kernel_launch(void* const* d_in, const int* in_sizes, int n_in,
                              void* d_out, int out_size)
{
    int i_logits = -1, i_sh = -1, i_bW = -1;
    int p2m[2] = {-1, -1};  int n2m = 0;
    int p32k[2] = {-1, -1}; int n32k = 0;
    int p1k[2] = {-1, -1};  int n1k = 0;
    int p1[2] = {-1, -1};   int n1 = 0;

    for (int i = 0; i < n_in; i++) {
        switch (in_sizes[i]) {
            case 65536000: i_logits = i; break;
            case 33554432: i_sh = i; break;
            case 2048:     i_bW = i; break;
            case 2097152:  if (n2m < 2) p2m[n2m++] = i; break;
            case 32768:    if (n32k < 2) p32k[n32k++] = i; break;
            case 1024:     if (n1k < 2) p1k[n1k++] = i; break;
            case 1:        if (n1 < 2) p1[n1++] = i; break;
            default: break;
        }
    }
    const bool alpha = (i_bW >= 0 && i_logits >= 0 && i_bW < i_logits);
    const int i_hidden = p2m[0],  i_mW1 = p2m[1];
    const int i_dist   = p32k[0], i_tok = p32k[1];
    const int i_bb     = p1[0],   i_mb2 = p1[1];
    const int i_mb1    = alpha ? p1k[1] : p1k[0];
    const int i_mW2    = alpha ? p1k[0] : p1k[1];

    const float* hidden = (const float*)d_in[i_hidden];
    const float* logits = (const float*)d_in[i_logits];
    const float* dist   = (const float*)d_in[i_dist];
    const float* sh     = (const float*)d_in[i_sh];
    const void*  tok    = d_in[i_tok];
    const float* bW     = (const float*)d_in[i_bW];
    const float* bb     = (const float*)d_in[i_bb];
    const float* mW1    = (const float*)d_in[i_mW1];
    const float* mb1    = (const float*)d_in[i_mb1];
    const float* mW2    = (const float*)d_in[i_mW2];
    const float* mb2    = (const float*)d_in[i_mb2];
    float*       out    = (float*)d_out;

    __nv_bfloat16 *hidden_h = nullptr, *mW1_h = nullptr, *merged_h = nullptr;
    cudaGetSymbolAddress((void**)&hidden_h, g_hidden_h);
    cudaGetSymbolAddress((void**)&mW1_h,   g_mW1_h);
    cudaGetSymbolAddress((void**)&merged_h, g_merged_h);

    cudaFuncSetAttribute(gemm_kernel, cudaFuncAttributeMaxDynamicSharedMemorySize, GEMM_SMEM);

    cudaStream_t s2;
    cudaStreamCreateWithFlags(&s2, cudaStreamNonBlocking);
    cudaEvent_t e0, e1, eSL, e2;
    cudaEventCreateWithFlags(&e0,  cudaEventDisableTiming);
    cudaEventCreateWithFlags(&e1,  cudaEventDisableTiming);
    cudaEventCreateWithFlags(&eSL, cudaEventDisableTiming);
    cudaEventCreateWithFlags(&e2,  cudaEventDisableTiming);

    cudaEventRecord(e0, 0);
    cudaStreamWaitEvent(s2, e0, 0);

    // S2: fused convert -> gemm0 -> (e1) gemm1 -> (eSL) low-half output tail.
    conv2_kernel<<<768, 256, 0, s2>>>(hidden, hidden_h, N_ROWS * DIM / 8,
                                      mW1, mW1_h, DIM * KTOT / 8);
    gemm_kernel<<<dim3(16, 8), 256, GEMM_SMEM, s2>>>(hidden_h, mb1, mW2, 0, 0);

    // Origin: prep -> (e1) -> stat_lo -> (eSL) -> stat_hi -> (e2) hi-half tail.
    prep_kernel<<<N_ROWS, 256>>>(hidden, dist, sh, bW, bb);
    cudaEventRecord(e1, 0);
    stat_kernel<<<HALF_ROWS, 256>>>(logits, 0);
    cudaEventRecord(eSL, 0);
    stat_kernel<<<HALF_ROWS, 256>>>(logits, HALF_ROWS);

    // S2: merged-half GEMM after prep, then low-half write pipeline.
    cudaStreamWaitEvent(s2, e1, 0);
    gemm_kernel<<<dim3(16, 8), 256, GEMM_SMEM, s2>>>(merged_h, mb1, mW2, DIM, 1);
    cudaEventRecord(e2, s2);
    cudaStreamWaitEvent(s2, eSL, 0);
    zfin_kernel<<<HALF_ROWS / 256, 256, 0, s2>>>(mb2, 0);
    write_kernel<<<HALF_ROWS * 4, 256, 0, s2>>>(logits, out, 0);
    fixup_kernel<<<HALF_ROWS, 32, 0, s2>>>(logits, tok, out, 0);

    // Origin: high-half write pipeline after gemm1.
    cudaStreamWaitEvent(0, e2, 0);
    zfin_kernel<<<HALF_ROWS / 256, 256>>>(mb2, HALF_ROWS);
    write_kernel<<<HALF_ROWS * 4, 256>>>(logits, out, HALF_ROWS);
    fixup_kernel<<<HALF_ROWS, 32>>>(logits, tok, out, HALF_ROWS);

    // Join: origin must also wait for s2's low-half tail before returning.
    cudaEventRecord(e0, s2);            // reuse e0 as s2-done marker
    cudaStreamWaitEvent(0, e0, 0);
}